// round 5
// baseline (speedup 1.0000x reference)
#include <cuda_runtime.h>
#include <cuda_bf16.h>
#include <cstdint>

// ===========================================================================
// Problem: B=32, T=128, F=1024, CONV_UNITS=2048, SHORT_UNITS=2048, RATE=4
//   out[b, 0:2016,    :] = memory[b, 32:2048,   :]
//   out[b, 2016:2048, :] = compression (GEMM)
//   out[b, 2048:3968, :] = memory[b, 2176:4096, :]
//   out[b, 3968:4096, :] = inputs[b, :, :]
// GEMM: C(1024x1024) = A(1024x4096) @ W(4096x1024) + bias
//   A row m=(b*32+t): 4096 contiguous floats at memory + b*2^22 + 2097152 + t*4096
//   W = conv_w viewed as (4096,1024) row-major.
//
// FUSED heterogeneous kernel: CTAs 0..127 run the GEMM (one per SM in wave 1,
// 78KB smem, tensor/LDS-bound); CTAs 128..2047 run the shifted copy
// (DRAM-bound). Complementary pipes -> overlap instead of serializing.
// ===========================================================================

#define CP_ASYNC16(dst, src) \
    asm volatile("cp.async.cg.shared.global [%0], [%1], 16;" \
                 :: "r"(dst), "l"(src) : "memory")
#define CP_ASYNC_COMMIT() asm volatile("cp.async.commit_group;" ::: "memory")
#define CP_ASYNC_WAIT1()  asm volatile("cp.async.wait_group 1;" ::: "memory")
#define CP_ASYNC_WAIT0()  asm volatile("cp.async.wait_group 0;" ::: "memory")

__device__ __forceinline__ uint32_t smem_u32(const void* p) {
    uint32_t a;
    asm("{ .reg .u64 t; cvta.to.shared.u64 t, %1; cvt.u32.u64 %0, t; }"
        : "=r"(a) : "l"(p));
    return a;
}

__device__ __forceinline__ void mma_tf32_16n8k8(float* c, const uint32_t* a,
                                                const uint32_t* b) {
    asm volatile(
        "mma.sync.aligned.m16n8k8.row.col.f32.tf32.tf32.f32 "
        "{%0,%1,%2,%3}, {%4,%5,%6,%7}, {%8,%9}, {%0,%1,%2,%3};"
        : "+f"(c[0]), "+f"(c[1]), "+f"(c[2]), "+f"(c[3])
        : "r"(a[0]), "r"(a[1]), "r"(a[2]), "r"(a[3]),
          "r"(b[0]), "r"(b[1]));
}

#define A_STRIDE 36
#define B_STRIDE 132
#define STAGE_BYTES 26112
#define NSTAGE 3
#define GEMM_CTAS 128
#define TOTAL_CTAS 2048

__global__ void __launch_bounds__(256, 2)
fused_kernel(const float* __restrict__ inputs,
             const float* __restrict__ memory,
             const float* __restrict__ W,
             const float* __restrict__ bias,
             float* __restrict__ out)
{
    const int tid = threadIdx.x;
    const int bid = blockIdx.x;

    if (bid >= GEMM_CTAS) {
        // ------------------------- COPY ROLE --------------------------------
        const float4* in4  = (const float4*)inputs;
        const float4* mem4 = (const float4*)memory;
        float4* out4 = (float4*)out;
        const unsigned total = 32u * 4096u * 256u;
        const unsigned stride = (TOTAL_CTAS - GEMM_CTAS) * 256u;
        for (unsigned v = (bid - GEMM_CTAS) * 256u + tid; v < total; v += stride) {
            unsigned f4 = v & 255u;
            unsigned rg = v >> 8;
            unsigned b  = rg >> 12;
            unsigned r  = rg & 4095u;
            float4 val;
            if (r < 2016u) {
                val = mem4[(b << 20) + ((r + 32u) << 8) + f4];
            } else if (r < 2048u) {
                continue;  // compression band written by GEMM CTAs
            } else if (r < 3968u) {
                val = mem4[(b << 20) + ((r + 128u) << 8) + f4];
            } else {
                val = in4[(b << 15) + ((r - 3968u) << 8) + f4];
            }
            out4[v] = val;
        }
        return;
    }

    // --------------------------- GEMM ROLE ---------------------------------
    extern __shared__ __align__(16) char smem[];
    const int wid = tid >> 5;
    const int lid = tid & 31;
    const int m0 = (bid >> 3) * 64;
    const int n0 = (bid & 7) * 128;
    const int wm = (wid & 1) * 32;
    const int wn = (wid >> 1) * 32;

    float acc[2][4][4];
#pragma unroll
    for (int i = 0; i < 2; i++)
#pragma unroll
        for (int j = 0; j < 4; j++)
#pragma unroll
            for (int k = 0; k < 4; k++) acc[i][j][k] = 0.0f;

    auto issue_stage = [&](int kc) {
        const int s = kc % NSTAGE;
        char* sa = smem + s * STAGE_BYTES;
        char* sb = sa + 9216;
        const int k0 = kc << 5;
#pragma unroll
        for (int rep = 0; rep < 2; rep++) {
            const int i = tid + rep * 256;
            const int r = i >> 3, q = i & 7;
            const int m = m0 + r;
            const float* src = memory + ((size_t)(m >> 5) << 22) + 2097152u
                               + ((size_t)(m & 31) << 12) + (unsigned)(k0 + (q << 2));
            CP_ASYNC16(smem_u32(sa + (r * A_STRIDE + q * 4) * 4), src);
        }
#pragma unroll
        for (int rep = 0; rep < 4; rep++) {
            const int i = tid + rep * 256;
            const int r = i >> 5, q = i & 31;
            const float* src = W + (size_t)(k0 + r) * 1024u + (unsigned)(n0 + (q << 2));
            CP_ASYNC16(smem_u32(sb + (r * B_STRIDE + q * 4) * 4), src);
        }
    };

    issue_stage(0); CP_ASYNC_COMMIT();
    issue_stage(1); CP_ASYNC_COMMIT();

    for (int kc = 0; kc < 128; ++kc) {
        CP_ASYNC_WAIT1();
        __syncthreads();

        if (kc + 2 < 128) issue_stage(kc + 2);
        CP_ASYNC_COMMIT();

        const int s = kc % NSTAGE;
        const float* sa = (const float*)(smem + s * STAGE_BYTES);
        const float* sb = (const float*)(smem + s * STAGE_BYTES + 9216);

#pragma unroll
        for (int ks = 0; ks < 4; ++ks) {
            const int k = ks << 3;
            uint32_t af[2][4], bf[4][2];
            const int arow = wm + (lid >> 2);
            const int acol = k + (lid & 3);
#pragma unroll
            for (int mt = 0; mt < 2; mt++) {
                const float* ap = sa + (arow + mt * 16) * A_STRIDE + acol;
                af[mt][0] = __float_as_uint(ap[0]);                  // A[g][t]
                af[mt][1] = __float_as_uint(ap[8 * A_STRIDE]);       // A[g+8][t]
                af[mt][2] = __float_as_uint(ap[4]);                  // A[g][t+4]
                af[mt][3] = __float_as_uint(ap[8 * A_STRIDE + 4]);   // A[g+8][t+4]
            }
            const int brow = k + (lid & 3);
            const int bcol = wn + (lid >> 2);
#pragma unroll
            for (int nt = 0; nt < 4; nt++) {
                const float* bp = sb + brow * B_STRIDE + bcol + nt * 8;
                bf[nt][0] = __float_as_uint(bp[0]);                  // B[t][g]
                bf[nt][1] = __float_as_uint(bp[4 * B_STRIDE]);       // B[t+4][g]
            }
#pragma unroll
            for (int mt = 0; mt < 2; mt++)
#pragma unroll
                for (int nt = 0; nt < 4; nt++)
                    mma_tf32_16n8k8(acc[mt][nt], af[mt], bf[nt]);
        }
        __syncthreads();
    }
    CP_ASYNC_WAIT0();

    // Epilogue: direct float2 stores into the compression band + bias.
#pragma unroll
    for (int mt = 0; mt < 2; mt++) {
#pragma unroll
        for (int nt = 0; nt < 4; nt++) {
            const int g = n0 + wn + nt * 8 + (lid & 3) * 2;
            const float2 bv = *(const float2*)(bias + g);
            const int m_lo = m0 + wm + mt * 16 + (lid >> 2);
            const int m_hi = m_lo + 8;
            float2 v0 = { acc[mt][nt][0] + bv.x, acc[mt][nt][1] + bv.y };
            float2 v1 = { acc[mt][nt][2] + bv.x, acc[mt][nt][3] + bv.y };
            *(float2*)(out + ((size_t)(m_lo >> 5) << 22)
                           + (size_t)(2016 + (m_lo & 31)) * 1024 + g) = v0;
            *(float2*)(out + ((size_t)(m_hi >> 5) << 22)
                           + (size_t)(2016 + (m_hi & 31)) * 1024 + g) = v1;
        }
    }
}

// ---------------------------------------------------------------------------
// Launch
// ---------------------------------------------------------------------------
extern "C" void kernel_launch(void* const* d_in, const int* in_sizes, int n_in,
                              void* d_out, int out_size)
{
    const float* inputs = (const float*)d_in[0];   // (32, 128, 1024)
    const float* memory = (const float*)d_in[1];   // (32, 4096, 1024)
    const float* conv_w = (const float*)d_in[2];   // (4, 1024, 1024)
    const float* conv_b = (const float*)d_in[3];   // (1024,)
    float* out = (float*)d_out;                    // (32, 4096, 1024)

    cudaFuncSetAttribute(fused_kernel,
                         cudaFuncAttributeMaxDynamicSharedMemorySize,
                         STAGE_BYTES * NSTAGE);

    fused_kernel<<<TOTAL_CTAS, 256, STAGE_BYTES * NSTAGE>>>(
        inputs, memory, conv_w, conv_b, out);
}

// round 6
// speedup vs baseline: 1.0948x; 1.0948x over previous
#include <cuda_runtime.h>
#include <cuda_bf16.h>
#include <cstdint>

// ===========================================================================
// Problem: B=32, T=128, F=1024, CONV_UNITS=2048, SHORT_UNITS=2048, RATE=4
//   out[b, 0:2016,    :] = memory[b, 32:2048,   :]
//   out[b, 2016:2048, :] = compression (GEMM)
//   out[b, 2048:3968, :] = memory[b, 2176:4096, :]
//   out[b, 3968:4096, :] = inputs[b, :, :]
// GEMM: C(1024x1024) = A(1024x4096) @ W(4096x1024) + bias
//   A row m=(b*32+t): 4096 contiguous floats at memory + b*2^22 + 2097152 + t*4096
//   W = conv_w viewed as (4096,1024) row-major.
//
// Two kernels launched on TWO forked streams inside graph capture so they run
// CONCURRENTLY: copy (DRAM-bound, 20 regs, 0 smem, full occupancy) overlaps
// the GEMM (tensor/LDS-bound, L2-resident operands). R5 showed fusing them
// into one kernel destroys copy occupancy (shared reg/smem budget).
// ===========================================================================

#define CP_ASYNC16(dst, src) \
    asm volatile("cp.async.cg.shared.global [%0], [%1], 16;" \
                 :: "r"(dst), "l"(src) : "memory")
#define CP_ASYNC_COMMIT() asm volatile("cp.async.commit_group;" ::: "memory")
#define CP_ASYNC_WAIT1()  asm volatile("cp.async.wait_group 1;" ::: "memory")
#define CP_ASYNC_WAIT0()  asm volatile("cp.async.wait_group 0;" ::: "memory")

__device__ __forceinline__ uint32_t smem_u32(const void* p) {
    uint32_t a;
    asm("{ .reg .u64 t; cvta.to.shared.u64 t, %1; cvt.u32.u64 %0, t; }"
        : "=r"(a) : "l"(p));
    return a;
}

__device__ __forceinline__ void mma_tf32_16n8k8(float* c, const uint32_t* a,
                                                const uint32_t* b) {
    asm volatile(
        "mma.sync.aligned.m16n8k8.row.col.f32.tf32.tf32.f32 "
        "{%0,%1,%2,%3}, {%4,%5,%6,%7}, {%8,%9}, {%0,%1,%2,%3};"
        : "+f"(c[0]), "+f"(c[1]), "+f"(c[2]), "+f"(c[3])
        : "r"(a[0]), "r"(a[1]), "r"(a[2]), "r"(a[3]),
          "r"(b[0]), "r"(b[1]));
}

#define A_STRIDE 36
#define B_STRIDE 132
#define STAGE_BYTES 26112
#define NSTAGE 3

// ---------------------------------------------------------------------------
// Pipelined tf32 GEMM. CTA tile 64x128, K-chunk 32, 3-stage cp.async.
// Grid (8,16) = 128 CTAs, 256 threads / 8 warps.
// PTX m16n8k8 tf32 A-fragment (g=lid>>2, t=lid&3):
//   a0=A[g][t] a1=A[g+8][t] a2=A[g][t+4] a3=A[g+8][t+4]
// B-fragment: b0=B[t][g], b1=B[t+4][g].  C: c0,c1=C[g][2t,2t+1]; c2,c3=C[g+8][..]
// ---------------------------------------------------------------------------
__global__ void __launch_bounds__(256, 1)
gemm_tf32(const float* __restrict__ memory,
          const float* __restrict__ W,
          const float* __restrict__ bias,
          float* __restrict__ out)
{
    extern __shared__ __align__(16) char smem[];
    const int tid = threadIdx.x;
    const int wid = tid >> 5;
    const int lid = tid & 31;
    const int m0 = blockIdx.y * 64;
    const int n0 = blockIdx.x * 128;
    const int wm = (wid & 1) * 32;
    const int wn = (wid >> 1) * 32;

    float acc[2][4][4];
#pragma unroll
    for (int i = 0; i < 2; i++)
#pragma unroll
        for (int j = 0; j < 4; j++)
#pragma unroll
            for (int k = 0; k < 4; k++) acc[i][j][k] = 0.0f;

    auto issue_stage = [&](int kc) {
        const int s = kc % NSTAGE;
        char* sa = smem + s * STAGE_BYTES;
        char* sb = sa + 9216;
        const int k0 = kc << 5;
#pragma unroll
        for (int rep = 0; rep < 2; rep++) {
            const int i = tid + rep * 256;
            const int r = i >> 3, q = i & 7;
            const int m = m0 + r;
            const float* src = memory + ((size_t)(m >> 5) << 22) + 2097152u
                               + ((size_t)(m & 31) << 12) + (unsigned)(k0 + (q << 2));
            CP_ASYNC16(smem_u32(sa + (r * A_STRIDE + q * 4) * 4), src);
        }
#pragma unroll
        for (int rep = 0; rep < 4; rep++) {
            const int i = tid + rep * 256;
            const int r = i >> 5, q = i & 31;
            const float* src = W + (size_t)(k0 + r) * 1024u + (unsigned)(n0 + (q << 2));
            CP_ASYNC16(smem_u32(sb + (r * B_STRIDE + q * 4) * 4), src);
        }
    };

    issue_stage(0); CP_ASYNC_COMMIT();
    issue_stage(1); CP_ASYNC_COMMIT();

    for (int kc = 0; kc < 128; ++kc) {
        CP_ASYNC_WAIT1();
        __syncthreads();

        if (kc + 2 < 128) issue_stage(kc + 2);
        CP_ASYNC_COMMIT();

        const int s = kc % NSTAGE;
        const float* sa = (const float*)(smem + s * STAGE_BYTES);
        const float* sb = (const float*)(smem + s * STAGE_BYTES + 9216);

#pragma unroll
        for (int ks = 0; ks < 4; ++ks) {
            const int k = ks << 3;
            uint32_t af[2][4], bf[4][2];
            const int arow = wm + (lid >> 2);
            const int acol = k + (lid & 3);
#pragma unroll
            for (int mt = 0; mt < 2; mt++) {
                const float* ap = sa + (arow + mt * 16) * A_STRIDE + acol;
                af[mt][0] = __float_as_uint(ap[0]);                  // A[g][t]
                af[mt][1] = __float_as_uint(ap[8 * A_STRIDE]);       // A[g+8][t]
                af[mt][2] = __float_as_uint(ap[4]);                  // A[g][t+4]
                af[mt][3] = __float_as_uint(ap[8 * A_STRIDE + 4]);   // A[g+8][t+4]
            }
            const int brow = k + (lid & 3);
            const int bcol = wn + (lid >> 2);
#pragma unroll
            for (int nt = 0; nt < 4; nt++) {
                const float* bp = sb + brow * B_STRIDE + bcol + nt * 8;
                bf[nt][0] = __float_as_uint(bp[0]);                  // B[t][g]
                bf[nt][1] = __float_as_uint(bp[4 * B_STRIDE]);       // B[t+4][g]
            }
#pragma unroll
            for (int mt = 0; mt < 2; mt++)
#pragma unroll
                for (int nt = 0; nt < 4; nt++)
                    mma_tf32_16n8k8(acc[mt][nt], af[mt], bf[nt]);
        }
        __syncthreads();
    }
    CP_ASYNC_WAIT0();

    // Epilogue: direct float2 stores into the compression band + bias.
#pragma unroll
    for (int mt = 0; mt < 2; mt++) {
#pragma unroll
        for (int nt = 0; nt < 4; nt++) {
            const int g = n0 + wn + nt * 8 + (lid & 3) * 2;
            const float2 bv = *(const float2*)(bias + g);
            const int m_lo = m0 + wm + mt * 16 + (lid >> 2);
            const int m_hi = m_lo + 8;
            float2 v0 = { acc[mt][nt][0] + bv.x, acc[mt][nt][1] + bv.y };
            float2 v1 = { acc[mt][nt][2] + bv.x, acc[mt][nt][3] + bv.y };
            *(float2*)(out + ((size_t)(m_lo >> 5) << 22)
                           + (size_t)(2016 + (m_lo & 31)) * 1024 + g) = v0;
            *(float2*)(out + ((size_t)(m_hi >> 5) << 22)
                           + (size_t)(2016 + (m_hi & 31)) * 1024 + g) = v1;
        }
    }
}

// ---------------------------------------------------------------------------
// Copy kernel: pure shifted memcpy, float4-vectorized, grid-stride.
// ---------------------------------------------------------------------------
__global__ void copy_kernel(const float4* __restrict__ inputs,
                            const float4* __restrict__ memory,
                            float4* __restrict__ out)
{
    const unsigned total = 32u * 4096u * 256u;
    const unsigned stride = gridDim.x * blockDim.x;
    for (unsigned v = blockIdx.x * blockDim.x + threadIdx.x; v < total; v += stride) {
        unsigned f4 = v & 255u;
        unsigned rg = v >> 8;
        unsigned b  = rg >> 12;
        unsigned r  = rg & 4095u;
        float4 val;
        if (r < 2016u) {
            val = memory[(b << 20) + ((r + 32u) << 8) + f4];
        } else if (r < 2048u) {
            continue;  // compression band written by GEMM kernel
        } else if (r < 3968u) {
            val = memory[(b << 20) + ((r + 128u) << 8) + f4];
        } else {
            val = inputs[(b << 15) + ((r - 3968u) << 8) + f4];
        }
        out[v] = val;
    }
}

// ---------------------------------------------------------------------------
// Launch: fork-join dual stream so copy and GEMM overlap (also valid inside
// graph capture -> two parallel graph nodes).
// ---------------------------------------------------------------------------
extern "C" void kernel_launch(void* const* d_in, const int* in_sizes, int n_in,
                              void* d_out, int out_size)
{
    const float* inputs = (const float*)d_in[0];   // (32, 128, 1024)
    const float* memory = (const float*)d_in[1];   // (32, 4096, 1024)
    const float* conv_w = (const float*)d_in[2];   // (4, 1024, 1024)
    const float* conv_b = (const float*)d_in[3];   // (1024,)
    float* out = (float*)d_out;                    // (32, 4096, 1024)

    static cudaStream_t s2 = nullptr;
    static cudaEvent_t eFork = nullptr, eJoin = nullptr;
    if (s2 == nullptr) {
        cudaStreamCreateWithFlags(&s2, cudaStreamNonBlocking);
        cudaEventCreateWithFlags(&eFork, cudaEventDisableTiming);
        cudaEventCreateWithFlags(&eJoin, cudaEventDisableTiming);
    }

    cudaFuncSetAttribute(gemm_tf32,
                         cudaFuncAttributeMaxDynamicSharedMemorySize,
                         STAGE_BYTES * NSTAGE);

    if (s2 != nullptr && eFork != nullptr && eJoin != nullptr) {
        // Fork: copy runs on s2 concurrently with the GEMM on the main stream.
        cudaEventRecord(eFork, 0);
        cudaStreamWaitEvent(s2, eFork, 0);
        copy_kernel<<<8192, 256, 0, s2>>>((const float4*)inputs,
                                          (const float4*)memory, (float4*)out);
        gemm_tf32<<<dim3(8, 16), 256, STAGE_BYTES * NSTAGE>>>(memory, conv_w,
                                                              conv_b, out);
        // Join back into the main (capture) stream.
        cudaEventRecord(eJoin, s2);
        cudaStreamWaitEvent(0, eJoin, 0);
    } else {
        // Fallback: serial launches (same work, same output).
        gemm_tf32<<<dim3(8, 16), 256, STAGE_BYTES * NSTAGE>>>(memory, conv_w,
                                                              conv_b, out);
        copy_kernel<<<8192, 256>>>((const float4*)inputs, (const float4*)memory,
                                   (float4*)out);
    }
}

// round 7
// speedup vs baseline: 1.1760x; 1.0741x over previous
#include <cuda_runtime.h>
#include <cuda_bf16.h>
#include <cstdint>

// ===========================================================================
// Problem: B=32, T=128, F=1024, CONV_UNITS=2048, SHORT_UNITS=2048, RATE=4
//   out[b, 0:2016,    :] = memory[b, 32:2048,   :]
//   out[b, 2016:2048, :] = compression (GEMM)
//   out[b, 2048:3968, :] = memory[b, 2176:4096, :]
//   out[b, 3968:4096, :] = inputs[b, :, :]
// GEMM: C(1024x1024) = A(1024x4096) @ W(4096x1024) + bias
//   A row m=(b*32+t): 4096 contiguous floats at memory + b*2^22 + 2097152 + t*4096
//   W = conv_w viewed as (4096,1024) row-major.
//
// R6 lesson: concurrent copy+GEMM collide on the L1tex/MIO path -> serial.
// R6 ncu: GEMM occ=12.5% was GRID-limited (128 CTAs < 148 SMs). This round:
// split-K 2 -> 256 CTAs -> 2 CTAs/SM (16 warps) to hide latency. Partials go
// to __device__ scratch (deterministic, no atomics); the copy kernel folds
// band = p0 + p1 + bias.
// ===========================================================================

#define CP_ASYNC16(dst, src) \
    asm volatile("cp.async.cg.shared.global [%0], [%1], 16;" \
                 :: "r"(dst), "l"(src) : "memory")
#define CP_ASYNC_COMMIT() asm volatile("cp.async.commit_group;" ::: "memory")
#define CP_ASYNC_WAIT1()  asm volatile("cp.async.wait_group 1;" ::: "memory")
#define CP_ASYNC_WAIT0()  asm volatile("cp.async.wait_group 0;" ::: "memory")

__device__ __forceinline__ uint32_t smem_u32(const void* p) {
    uint32_t a;
    asm("{ .reg .u64 t; cvta.to.shared.u64 t, %1; cvt.u32.u64 %0, t; }"
        : "=r"(a) : "l"(p));
    return a;
}

__device__ __forceinline__ void mma_tf32_16n8k8(float* c, const uint32_t* a,
                                                const uint32_t* b) {
    asm volatile(
        "mma.sync.aligned.m16n8k8.row.col.f32.tf32.tf32.f32 "
        "{%0,%1,%2,%3}, {%4,%5,%6,%7}, {%8,%9}, {%0,%1,%2,%3};"
        : "+f"(c[0]), "+f"(c[1]), "+f"(c[2]), "+f"(c[3])
        : "r"(a[0]), "r"(a[1]), "r"(a[2]), "r"(a[3]),
          "r"(b[0]), "r"(b[1]));
}

#define A_STRIDE 36
#define B_STRIDE 132
#define STAGE_BYTES 26112
#define NSTAGE 3
#define KC_PER_SPLIT 64   // 128 K-chunks total, 2-way split-K

// Split-K partial sums: 2 x 1024 x 1024 f32 = 8 MB device scratch.
__device__ float g_part[2 * 1024 * 1024];

// ---------------------------------------------------------------------------
// Pipelined tf32 GEMM, split-K 2. CTA tile 64x128, K-chunk 32, 3-stage
// cp.async. Grid (8,16,2) = 256 CTAs -> 2 CTAs/SM. 256 threads / 8 warps.
// PTX m16n8k8 tf32 A-fragment (g=lid>>2, t=lid&3):
//   a0=A[g][t] a1=A[g+8][t] a2=A[g][t+4] a3=A[g+8][t+4]
// B-fragment: b0=B[t][g], b1=B[t+4][g].  C: c0,c1=C[g][2t,2t+1]; c2,c3=C[g+8][..]
// ---------------------------------------------------------------------------
__global__ void __launch_bounds__(256, 2)
gemm_tf32(const float* __restrict__ memory,
          const float* __restrict__ W)
{
    extern __shared__ __align__(16) char smem[];
    const int tid = threadIdx.x;
    const int wid = tid >> 5;
    const int lid = tid & 31;
    const int m0 = blockIdx.y * 64;
    const int n0 = blockIdx.x * 128;
    const int kz = blockIdx.z;           // split-K index 0/1
    const int kc_base = kz * KC_PER_SPLIT;
    const int wm = (wid & 1) * 32;
    const int wn = (wid >> 1) * 32;

    float acc[2][4][4];
#pragma unroll
    for (int i = 0; i < 2; i++)
#pragma unroll
        for (int j = 0; j < 4; j++)
#pragma unroll
            for (int k = 0; k < 4; k++) acc[i][j][k] = 0.0f;

    auto issue_stage = [&](int kc2) {
        const int s = kc2 % NSTAGE;
        char* sa = smem + s * STAGE_BYTES;
        char* sb = sa + 9216;
        const int k0 = (kc_base + kc2) << 5;
#pragma unroll
        for (int rep = 0; rep < 2; rep++) {
            const int i = tid + rep * 256;
            const int r = i >> 3, q = i & 7;
            const int m = m0 + r;
            const float* src = memory + ((size_t)(m >> 5) << 22) + 2097152u
                               + ((size_t)(m & 31) << 12) + (unsigned)(k0 + (q << 2));
            CP_ASYNC16(smem_u32(sa + (r * A_STRIDE + q * 4) * 4), src);
        }
#pragma unroll
        for (int rep = 0; rep < 4; rep++) {
            const int i = tid + rep * 256;
            const int r = i >> 5, q = i & 31;
            const float* src = W + (size_t)(k0 + r) * 1024u + (unsigned)(n0 + (q << 2));
            CP_ASYNC16(smem_u32(sb + (r * B_STRIDE + q * 4) * 4), src);
        }
    };

    issue_stage(0); CP_ASYNC_COMMIT();
    issue_stage(1); CP_ASYNC_COMMIT();

    for (int kc2 = 0; kc2 < KC_PER_SPLIT; ++kc2) {
        CP_ASYNC_WAIT1();
        __syncthreads();

        if (kc2 + 2 < KC_PER_SPLIT) issue_stage(kc2 + 2);
        CP_ASYNC_COMMIT();

        const int s = kc2 % NSTAGE;
        const float* sa = (const float*)(smem + s * STAGE_BYTES);
        const float* sb = (const float*)(smem + s * STAGE_BYTES + 9216);

#pragma unroll
        for (int ks = 0; ks < 4; ++ks) {
            const int k = ks << 3;
            uint32_t af[2][4], bf[4][2];
            const int arow = wm + (lid >> 2);
            const int acol = k + (lid & 3);
#pragma unroll
            for (int mt = 0; mt < 2; mt++) {
                const float* ap = sa + (arow + mt * 16) * A_STRIDE + acol;
                af[mt][0] = __float_as_uint(ap[0]);                  // A[g][t]
                af[mt][1] = __float_as_uint(ap[8 * A_STRIDE]);       // A[g+8][t]
                af[mt][2] = __float_as_uint(ap[4]);                  // A[g][t+4]
                af[mt][3] = __float_as_uint(ap[8 * A_STRIDE + 4]);   // A[g+8][t+4]
            }
            const int brow = k + (lid & 3);
            const int bcol = wn + (lid >> 2);
#pragma unroll
            for (int nt = 0; nt < 4; nt++) {
                const float* bp = sb + brow * B_STRIDE + bcol + nt * 8;
                bf[nt][0] = __float_as_uint(bp[0]);                  // B[t][g]
                bf[nt][1] = __float_as_uint(bp[4 * B_STRIDE]);       // B[t+4][g]
            }
#pragma unroll
            for (int mt = 0; mt < 2; mt++)
#pragma unroll
                for (int nt = 0; nt < 4; nt++)
                    mma_tf32_16n8k8(acc[mt][nt], af[mt], bf[nt]);
        }
        __syncthreads();
    }
    CP_ASYNC_WAIT0();

    // Epilogue: partial sums to scratch (no bias; copy kernel folds it).
    float* part = g_part + (size_t)kz * 1048576u;
#pragma unroll
    for (int mt = 0; mt < 2; mt++) {
#pragma unroll
        for (int nt = 0; nt < 4; nt++) {
            const int g = n0 + wn + nt * 8 + (lid & 3) * 2;
            const int m_lo = m0 + wm + mt * 16 + (lid >> 2);
            const int m_hi = m_lo + 8;
            float2 v0 = { acc[mt][nt][0], acc[mt][nt][1] };
            float2 v1 = { acc[mt][nt][2], acc[mt][nt][3] };
            *(float2*)(part + (size_t)m_lo * 1024 + g) = v0;
            *(float2*)(part + (size_t)m_hi * 1024 + g) = v1;
        }
    }
}

// ---------------------------------------------------------------------------
// Copy kernel: shifted memcpy + split-K reduction for the compression band.
// ---------------------------------------------------------------------------
__global__ void copy_kernel(const float4* __restrict__ inputs,
                            const float4* __restrict__ memory,
                            const float4* __restrict__ bias,
                            float4* __restrict__ out)
{
    const float4* p0 = (const float4*)g_part;
    const float4* p1 = p0 + 262144;   // 1M floats = 256K float4
    const unsigned total = 32u * 4096u * 256u;
    const unsigned stride = gridDim.x * blockDim.x;
    for (unsigned v = blockIdx.x * blockDim.x + threadIdx.x; v < total; v += stride) {
        unsigned f4 = v & 255u;
        unsigned rg = v >> 8;
        unsigned b  = rg >> 12;
        unsigned r  = rg & 4095u;
        float4 val;
        if (r < 2016u) {
            val = memory[(b << 20) + ((r + 32u) << 8) + f4];
        } else if (r < 2048u) {
            // compression band: fold split-K partials + bias
            unsigned m = (b << 5) + (r - 2016u);      // C row
            unsigned ci = (m << 8) + f4;
            float4 a = p0[ci], c = p1[ci], bb = bias[f4];
            val.x = a.x + c.x + bb.x;
            val.y = a.y + c.y + bb.y;
            val.z = a.z + c.z + bb.z;
            val.w = a.w + c.w + bb.w;
        } else if (r < 3968u) {
            val = memory[(b << 20) + ((r + 128u) << 8) + f4];
        } else {
            val = inputs[(b << 15) + ((r - 3968u) << 8) + f4];
        }
        out[v] = val;
    }
}

// ---------------------------------------------------------------------------
// Launch: serial — GEMM (split-K partials) then copy (folds band).
// ---------------------------------------------------------------------------
extern "C" void kernel_launch(void* const* d_in, const int* in_sizes, int n_in,
                              void* d_out, int out_size)
{
    const float* inputs = (const float*)d_in[0];   // (32, 128, 1024)
    const float* memory = (const float*)d_in[1];   // (32, 4096, 1024)
    const float* conv_w = (const float*)d_in[2];   // (4, 1024, 1024)
    const float* conv_b = (const float*)d_in[3];   // (1024,)
    float* out = (float*)d_out;                    // (32, 4096, 1024)

    cudaFuncSetAttribute(gemm_tf32,
                         cudaFuncAttributeMaxDynamicSharedMemorySize,
                         STAGE_BYTES * NSTAGE);

    gemm_tf32<<<dim3(8, 16, 2), 256, STAGE_BYTES * NSTAGE>>>(memory, conv_w);
    copy_kernel<<<8192, 256>>>((const float4*)inputs, (const float4*)memory,
                               (const float4*)conv_b, (float4*)out);
}

// round 8
// speedup vs baseline: 1.4116x; 1.2003x over previous
#include <cuda_runtime.h>
#include <cuda_bf16.h>
#include <cstdint>

// ===========================================================================
// Problem: B=32, T=128, F=1024, CONV_UNITS=2048, SHORT_UNITS=2048, RATE=4
//   out[b, 0:2016,    :] = memory[b, 32:2048,   :]
//   out[b, 2016:2048, :] = compression (GEMM)
//   out[b, 2048:3968, :] = memory[b, 2176:4096, :]
//   out[b, 3968:4096, :] = inputs[b, :, :]
// GEMM: C(1024x1024) = A(1024x4096) @ W(4096x1024) + bias
//   A row m=(b*32+t): 4096 contiguous floats at memory + b*2^22 + 2097152 + t*4096
//   W = conv_w viewed as (4096,1024) row-major.
//
// R7 lessons: split-K across CTAs loses (L2 thrash, ragged waves, shared
// crossbar); copy+GEMM concurrency loses (L1tex contention). Serial, 128
// GEMM CTAs, 1/SM. This round: warp decomposition 2x2 spatial (32x64 warp
// tile) x 2-way intra-CTA K-split -> 1.5 LDS/MMA (was 2.0) and 16-MMA ILP
// blocks (was 8), smem reduction at end.
// ===========================================================================

#define CP_ASYNC16(dst, src) \
    asm volatile("cp.async.cg.shared.global [%0], [%1], 16;" \
                 :: "r"(dst), "l"(src) : "memory")
#define CP_ASYNC_COMMIT() asm volatile("cp.async.commit_group;" ::: "memory")
#define CP_ASYNC_WAIT1()  asm volatile("cp.async.wait_group 1;" ::: "memory")
#define CP_ASYNC_WAIT0()  asm volatile("cp.async.wait_group 0;" ::: "memory")

__device__ __forceinline__ uint32_t smem_u32(const void* p) {
    uint32_t a;
    asm("{ .reg .u64 t; cvta.to.shared.u64 t, %1; cvt.u32.u64 %0, t; }"
        : "=r"(a) : "l"(p));
    return a;
}

__device__ __forceinline__ void mma_tf32_16n8k8(float* c, const uint32_t* a,
                                                const uint32_t* b) {
    asm volatile(
        "mma.sync.aligned.m16n8k8.row.col.f32.tf32.tf32.f32 "
        "{%0,%1,%2,%3}, {%4,%5,%6,%7}, {%8,%9}, {%0,%1,%2,%3};"
        : "+f"(c[0]), "+f"(c[1]), "+f"(c[2]), "+f"(c[3])
        : "r"(a[0]), "r"(a[1]), "r"(a[2]), "r"(a[3]),
          "r"(b[0]), "r"(b[1]));
}

#define A_STRIDE 36
#define B_STRIDE 132
#define STAGE_BYTES 26112
#define NSTAGE 3

// ---------------------------------------------------------------------------
// Pipelined tf32 GEMM. CTA tile 64x128, K-chunk 32, 3-stage cp.async.
// Grid (8,16) = 128 CTAs, 256 threads / 8 warps.
// Warp map: ws = wid&3 spatial (wm=(ws&1)*32, wn=(ws>>1)*64, warp tile 32x64);
//           kh = wid>>2 K-half (ks = 2*kh + ks2). End: kh=1 partials reduced
//           into kh=0 via smem, then bias + store.
// PTX m16n8k8 tf32 A-fragment (g=lid>>2, t=lid&3):
//   a0=A[g][t] a1=A[g+8][t] a2=A[g][t+4] a3=A[g+8][t+4]
// B-fragment: b0=B[t][g], b1=B[t+4][g].  C: c0,c1=C[g][2t,2t+1]; c2,c3=C[g+8][..]
// ---------------------------------------------------------------------------
__global__ void __launch_bounds__(256, 1)
gemm_tf32(const float* __restrict__ memory,
          const float* __restrict__ W,
          const float* __restrict__ bias,
          float* __restrict__ out)
{
    extern __shared__ __align__(16) char smem[];
    const int tid = threadIdx.x;
    const int wid = tid >> 5;
    const int lid = tid & 31;
    const int m0 = blockIdx.y * 64;
    const int n0 = blockIdx.x * 128;
    const int ws = wid & 3;
    const int kh = wid >> 2;
    const int wm = (ws & 1) * 32;
    const int wn = (ws >> 1) * 64;

    float acc[2][8][4];
#pragma unroll
    for (int i = 0; i < 2; i++)
#pragma unroll
        for (int j = 0; j < 8; j++)
#pragma unroll
            for (int k = 0; k < 4; k++) acc[i][j][k] = 0.0f;

    auto issue_stage = [&](int kc) {
        const int s = kc % NSTAGE;
        char* sa = smem + s * STAGE_BYTES;
        char* sb = sa + 9216;
        const int k0 = kc << 5;
#pragma unroll
        for (int rep = 0; rep < 2; rep++) {
            const int i = tid + rep * 256;
            const int r = i >> 3, q = i & 7;
            const int m = m0 + r;
            const float* src = memory + ((size_t)(m >> 5) << 22) + 2097152u
                               + ((size_t)(m & 31) << 12) + (unsigned)(k0 + (q << 2));
            CP_ASYNC16(smem_u32(sa + (r * A_STRIDE + q * 4) * 4), src);
        }
#pragma unroll
        for (int rep = 0; rep < 4; rep++) {
            const int i = tid + rep * 256;
            const int r = i >> 5, q = i & 31;
            const float* src = W + (size_t)(k0 + r) * 1024u + (unsigned)(n0 + (q << 2));
            CP_ASYNC16(smem_u32(sb + (r * B_STRIDE + q * 4) * 4), src);
        }
    };

    issue_stage(0); CP_ASYNC_COMMIT();
    issue_stage(1); CP_ASYNC_COMMIT();

    for (int kc = 0; kc < 128; ++kc) {
        CP_ASYNC_WAIT1();
        __syncthreads();

        if (kc + 2 < 128) issue_stage(kc + 2);
        CP_ASYNC_COMMIT();

        const int s = kc % NSTAGE;
        const float* sa = (const float*)(smem + s * STAGE_BYTES);
        const float* sb = (const float*)(smem + s * STAGE_BYTES + 9216);

#pragma unroll
        for (int ks2 = 0; ks2 < 2; ++ks2) {
            const int k = (kh * 2 + ks2) << 3;
            uint32_t af[2][4], bf[8][2];
            const int arow = wm + (lid >> 2);
            const int acol = k + (lid & 3);
#pragma unroll
            for (int mt = 0; mt < 2; mt++) {
                const float* ap = sa + (arow + mt * 16) * A_STRIDE + acol;
                af[mt][0] = __float_as_uint(ap[0]);                  // A[g][t]
                af[mt][1] = __float_as_uint(ap[8 * A_STRIDE]);       // A[g+8][t]
                af[mt][2] = __float_as_uint(ap[4]);                  // A[g][t+4]
                af[mt][3] = __float_as_uint(ap[8 * A_STRIDE + 4]);   // A[g+8][t+4]
            }
            const int brow = k + (lid & 3);
            const int bcol = wn + (lid >> 2);
#pragma unroll
            for (int nt = 0; nt < 8; nt++) {
                const float* bp = sb + brow * B_STRIDE + bcol + nt * 8;
                bf[nt][0] = __float_as_uint(bp[0]);                  // B[t][g]
                bf[nt][1] = __float_as_uint(bp[4 * B_STRIDE]);       // B[t+4][g]
            }
#pragma unroll
            for (int mt = 0; mt < 2; mt++)
#pragma unroll
                for (int nt = 0; nt < 8; nt++)
                    mma_tf32_16n8k8(acc[mt][nt], af[mt], bf[nt]);
        }
        __syncthreads();
    }
    CP_ASYNC_WAIT0();
    __syncthreads();   // all compute done; stage buffers reusable as reduction scratch

    // Intra-CTA K-split reduction: kh=1 warps dump partials, kh=0 warps fold.
    float* red = (float*)smem;          // 4 tiles x 2048 floats = 32KB
    if (kh == 1) {
#pragma unroll
        for (int mt = 0; mt < 2; mt++)
#pragma unroll
            for (int nt = 0; nt < 8; nt++)
#pragma unroll
                for (int c = 0; c < 4; c++) {
                    const int r = mt * 32 + nt * 4 + c;
                    red[ws * 2048 + r * 32 + lid] = acc[mt][nt][c];
                }
    }
    __syncthreads();
    if (kh == 0) {
#pragma unroll
        for (int mt = 0; mt < 2; mt++)
#pragma unroll
            for (int nt = 0; nt < 8; nt++)
#pragma unroll
                for (int c = 0; c < 4; c++) {
                    const int r = mt * 32 + nt * 4 + c;
                    acc[mt][nt][c] += red[ws * 2048 + r * 32 + lid];
                }

        // Epilogue: bias + direct float2 stores into the compression band.
#pragma unroll
        for (int mt = 0; mt < 2; mt++) {
#pragma unroll
            for (int nt = 0; nt < 8; nt++) {
                const int g = n0 + wn + nt * 8 + (lid & 3) * 2;
                const float2 bv = *(const float2*)(bias + g);
                const int m_lo = m0 + wm + mt * 16 + (lid >> 2);
                const int m_hi = m_lo + 8;
                float2 v0 = { acc[mt][nt][0] + bv.x, acc[mt][nt][1] + bv.y };
                float2 v1 = { acc[mt][nt][2] + bv.x, acc[mt][nt][3] + bv.y };
                *(float2*)(out + ((size_t)(m_lo >> 5) << 22)
                               + (size_t)(2016 + (m_lo & 31)) * 1024 + g) = v0;
                *(float2*)(out + ((size_t)(m_hi >> 5) << 22)
                               + (size_t)(2016 + (m_hi & 31)) * 1024 + g) = v1;
            }
        }
    }
}

// ---------------------------------------------------------------------------
// Copy kernel: pure shifted memcpy, float4-vectorized, grid-stride (R4 form).
// ---------------------------------------------------------------------------
__global__ void copy_kernel(const float4* __restrict__ inputs,
                            const float4* __restrict__ memory,
                            float4* __restrict__ out)
{
    const unsigned total = 32u * 4096u * 256u;
    const unsigned stride = gridDim.x * blockDim.x;
    for (unsigned v = blockIdx.x * blockDim.x + threadIdx.x; v < total; v += stride) {
        unsigned f4 = v & 255u;
        unsigned rg = v >> 8;
        unsigned b  = rg >> 12;
        unsigned r  = rg & 4095u;
        float4 val;
        if (r < 2016u) {
            val = memory[(b << 20) + ((r + 32u) << 8) + f4];
        } else if (r < 2048u) {
            continue;  // compression band written by GEMM kernel
        } else if (r < 3968u) {
            val = memory[(b << 20) + ((r + 128u) << 8) + f4];
        } else {
            val = inputs[(b << 15) + ((r - 3968u) << 8) + f4];
        }
        out[v] = val;
    }
}

// ---------------------------------------------------------------------------
// Launch: serial — GEMM then copy.
// ---------------------------------------------------------------------------
extern "C" void kernel_launch(void* const* d_in, const int* in_sizes, int n_in,
                              void* d_out, int out_size)
{
    const float* inputs = (const float*)d_in[0];   // (32, 128, 1024)
    const float* memory = (const float*)d_in[1];   // (32, 4096, 1024)
    const float* conv_w = (const float*)d_in[2];   // (4, 1024, 1024)
    const float* conv_b = (const float*)d_in[3];   // (1024,)
    float* out = (float*)d_out;                    // (32, 4096, 1024)

    cudaFuncSetAttribute(gemm_tf32,
                         cudaFuncAttributeMaxDynamicSharedMemorySize,
                         STAGE_BYTES * NSTAGE);

    gemm_tf32<<<dim3(8, 16), 256, STAGE_BYTES * NSTAGE>>>(memory, conv_w,
                                                          conv_b, out);
    copy_kernel<<<8192, 256>>>((const float4*)inputs, (const float4*)memory,
                               (float4*)out);
}